// round 3
// baseline (speedup 1.0000x reference)
#include <cuda_runtime.h>

// ---------------------------------------------------------------------------
// Problem constants (fixed by the dataset)
//   N=50000 nodes, E=1000000 edges, R=8 relations, B=30 bases, DIN=H1=H2=64
// NOTE: edge_index / edge_type are int32 (JAX default x64-disabled demotes
//       astype(int64) to int32).
// ---------------------------------------------------------------------------
#define NMAX 50000
#define RCOLS 512            // 8 relations * 64
#define WCOLS 576            // + self-loop slice

// Scratch (device globals; no allocation allowed). 16B-aligned for float4/red.v4.
__device__ __align__(16) float g_W[64 * WCOLS];               // [DIN][R*H1 + H1]
__device__ __align__(16) float g_xr[(long long)NMAX * RCOLS]; // [N][512]
__device__ __align__(16) float g_agg1[NMAX * 64];             // h after layer 1
__device__ __align__(16) float g_hs[NMAX * 64];               // h * rsqrt(deg_out)
__device__ __align__(16) float g_agg2[NMAX * 64];             // layer-2 neighbor sum
__device__ float g_deg_out[NMAX];
__device__ float g_deg_in[NMAX];

// ---------------------------------------------------------------------------
// Packed f32x2 helpers (Blackwell fma.rn.f32x2: 2x fp32 FMA lanes per instr)
// ---------------------------------------------------------------------------
__device__ __forceinline__ void fma2(unsigned long long &d,
                                     unsigned long long a,
                                     unsigned long long b) {
    asm("fma.rn.f32x2 %0, %1, %2, %0;" : "+l"(d) : "l"(a), "l"(b));
}
__device__ __forceinline__ unsigned long long bcast2(float x) {
    unsigned long long r;
    unsigned u = __float_as_uint(x);
    asm("mov.b64 %0, {%1, %1};" : "=l"(r) : "r"(u));
    return r;
}
__device__ __forceinline__ void unpack2(unsigned long long v, float &lo, float &hi) {
    unsigned a, b;
    asm("mov.b64 {%0, %1}, %2;" : "=r"(a), "=r"(b) : "l"(v));
    lo = __uint_as_float(a);
    hi = __uint_as_float(b);
}
// Vectorized global reduction (sm_90+): 4 floats per atomic op
__device__ __forceinline__ void red4(float *p, float4 v) {
    asm volatile("red.global.add.v4.f32 [%0], {%1, %2, %3, %4};"
                 :: "l"(p), "f"(v.x), "f"(v.y), "f"(v.z), "f"(v.w) : "memory");
}

// ---------------------------------------------------------------------------
// Small kernels
// ---------------------------------------------------------------------------
__global__ void zero_deg_kernel(int n) {
    int i = blockIdx.x * blockDim.x + threadIdx.x;
    if (i < n) { g_deg_out[i] = 0.f; g_deg_in[i] = 0.f; }
}

// g_W[i][r*64+o] = sum_b comp[r,b] * basis[b,i,o];  g_W[i][512+o] = loop_weight[i,o]
__global__ void build_w_kernel(const float *__restrict__ basis,
                               const float *__restrict__ comp,
                               const float *__restrict__ loopw) {
    int id = blockIdx.x * blockDim.x + threadIdx.x;
    if (id >= 64 * WCOLS) return;
    int i = id / WCOLS, c = id % WCOLS;
    if (c < RCOLS) {
        int r = c >> 6, o = c & 63;
        float s = 0.f;
#pragma unroll
        for (int b = 0; b < 30; ++b)
            s += comp[r * 30 + b] * basis[b * 4096 + i * 64 + o];
        g_W[i * WCOLS + c] = s;
    } else {
        g_W[i * WCOLS + c] = loopw[i * 64 + (c - RCOLS)];
    }
}

__global__ void deg_kernel(const int *__restrict__ ei, int E) {
    int e = blockIdx.x * blockDim.x + threadIdx.x;
    if (e >= E) return;
    int s = ei[e], d = ei[E + e];
    atomicAdd(&g_deg_out[s], 1.f);
    atomicAdd(&g_deg_in[d], 1.f);
}

// hs = agg1 * rsqrt(max(deg_out,1));  also zero agg2 for the next scatter
__global__ void hs_kernel(int n) {
    int idx = blockIdx.x * blockDim.x + threadIdx.x;
    if (idx >= n * 16) return;
    int node = idx >> 4, j = (idx & 15) * 4;
    float s = rsqrtf(fmaxf(g_deg_out[node], 1.f));
    float4 v = *(const float4 *)(g_agg1 + node * 64 + j);
    v.x *= s; v.y *= s; v.z *= s; v.w *= s;
    *(float4 *)(g_hs + node * 64 + j) = v;
    *(float4 *)(g_agg2 + node * 64 + j) = make_float4(0.f, 0.f, 0.f, 0.f);
}

// ---------------------------------------------------------------------------
// Edge scatter kernels: 8 threads per edge, 8 floats (2x float4) each.
// ---------------------------------------------------------------------------
__global__ void edge1_kernel(const int *__restrict__ ei,
                             const int *__restrict__ et, int E) {
    int idx = blockIdx.x * blockDim.x + threadIdx.x;
    int e = idx >> 3;
    if (e >= E) return;
    int part = idx & 7;
    int s = ei[e], d = ei[E + e], r = et[e];
    const float4 *src = (const float4 *)(g_xr + s * RCOLS + r * 64 + part * 8);
    float *dst = g_agg1 + d * 64 + part * 8;
    red4(dst, src[0]);
    red4(dst + 4, src[1]);
}

__global__ void edge2_kernel(const int *__restrict__ ei, int E) {
    int idx = blockIdx.x * blockDim.x + threadIdx.x;
    int e = idx >> 3;
    if (e >= E) return;
    int part = idx & 7;
    int s = ei[e], d = ei[E + e];
    const float4 *src = (const float4 *)(g_hs + s * 64 + part * 8);
    float *dst = g_agg2 + d * 64 + part * 8;
    red4(dst, src[0]);
    red4(dst + 4, src[1]);
}

// ---------------------------------------------------------------------------
// GEMM 1: xr[N,576] = X[N,64] @ g_W[64,576]   (col-tile 8 -> agg1 = v + bias1)
// Tile: 128 rows x 64 cols per CTA, K=64, packed f32x2 accumulation.
// Smem: XsT (transposed A, 64x128) + Ws (64x64) = exactly 48KB.
// ---------------------------------------------------------------------------
__global__ __launch_bounds__(256) void gemm1_kernel(const float *__restrict__ X,
                                                    const float *__restrict__ bias1,
                                                    int n) {
    __shared__ __align__(16) float XsT[64][128];
    __shared__ __align__(16) float Ws[64][64];
    int t = threadIdx.x;
    int rowbase = blockIdx.x * 128;
    int ctile = blockIdx.y;  // 0..8

    {   // Load A tile, store transposed
        int rl = t & 15, cg = t >> 4;   // cg: 0..15 -> 4-col group
#pragma unroll
        for (int it = 0; it < 8; ++it) {
            int r = rl + it * 16;
            int grow = rowbase + r;
            float4 v = make_float4(0.f, 0.f, 0.f, 0.f);
            if (grow < n) v = *(const float4 *)(X + grow * 64 + cg * 4);
            XsT[cg * 4 + 0][r] = v.x;
            XsT[cg * 4 + 1][r] = v.y;
            XsT[cg * 4 + 2][r] = v.z;
            XsT[cg * 4 + 3][r] = v.w;
        }
    }
    {   // Load W col-tile
        int c4 = (t & 15) * 4, kl = t >> 4;
#pragma unroll
        for (int it = 0; it < 4; ++it) {
            int k = kl + it * 16;
            *(float4 *)&Ws[k][c4] =
                *(const float4 *)(g_W + k * WCOLS + ctile * 64 + c4);
        }
    }
    __syncthreads();

    int tc = t & 15, tr = t >> 4;
    int c0 = tc * 4, r0 = tr * 8;                 // 8 rows x 4 cols per thread
    unsigned long long acc[4][4];
#pragma unroll
    for (int p = 0; p < 4; ++p)
#pragma unroll
        for (int j = 0; j < 4; ++j) acc[p][j] = 0ULL;

#pragma unroll 16
    for (int k = 0; k < 64; ++k) {
        ulonglong2 xa = *(const ulonglong2 *)&XsT[k][r0];       // rows r0..r0+3
        ulonglong2 xb = *(const ulonglong2 *)&XsT[k][r0 + 4];   // rows r0+4..r0+7
        float4 w = *(const float4 *)&Ws[k][c0];
        unsigned long long wd0 = bcast2(w.x), wd1 = bcast2(w.y);
        unsigned long long wd2 = bcast2(w.z), wd3 = bcast2(w.w);
        unsigned long long xp[4] = {xa.x, xa.y, xb.x, xb.y};
#pragma unroll
        for (int p = 0; p < 4; ++p) {
            fma2(acc[p][0], xp[p], wd0);
            fma2(acc[p][1], xp[p], wd1);
            fma2(acc[p][2], xp[p], wd2);
            fma2(acc[p][3], xp[p], wd3);
        }
    }

#pragma unroll
    for (int p = 0; p < 4; ++p) {
        int rA = rowbase + r0 + 2 * p;   // acc pair = rows (rA, rA+1)
#pragma unroll
        for (int j = 0; j < 4; ++j) {
            float lo, hi;
            unpack2(acc[p][j], lo, hi);
            int col = c0 + j;
            if (ctile < 8) {
                if (rA < n)     g_xr[rA * RCOLS + ctile * 64 + col] = lo;
                if (rA + 1 < n) g_xr[(rA + 1) * RCOLS + ctile * 64 + col] = hi;
            } else {  // self-loop slice: seed agg1 = loop term + bias1
                float b = bias1[col];
                if (rA < n)     g_agg1[rA * 64 + col] = lo + b;
                if (rA + 1 < n) g_agg1[(rA + 1) * 64 + col] = hi + b;
            }
        }
    }
}

// ---------------------------------------------------------------------------
// GEMM 2: out[N,64] = (agg2 * rsqrt(max(deg_in,1))) @ W2 + bias2
// ---------------------------------------------------------------------------
__global__ __launch_bounds__(256) void gemm2_kernel(const float *__restrict__ W2,
                                                    const float *__restrict__ bias2,
                                                    float *__restrict__ out,
                                                    int n) {
    __shared__ __align__(16) float XsT[64][128];
    __shared__ __align__(16) float Ws[64][64];
    int t = threadIdx.x;
    int rowbase = blockIdx.x * 128;

    {
        int rl = t & 15, cg = t >> 4;
#pragma unroll
        for (int it = 0; it < 8; ++it) {
            int r = rl + it * 16;
            int grow = rowbase + r;
            float4 v = make_float4(0.f, 0.f, 0.f, 0.f);
            if (grow < n) {
                v = *(const float4 *)(g_agg2 + grow * 64 + cg * 4);
                float s = rsqrtf(fmaxf(g_deg_in[grow], 1.f));
                v.x *= s; v.y *= s; v.z *= s; v.w *= s;
            }
            XsT[cg * 4 + 0][r] = v.x;
            XsT[cg * 4 + 1][r] = v.y;
            XsT[cg * 4 + 2][r] = v.z;
            XsT[cg * 4 + 3][r] = v.w;
        }
    }
    {
        int c4 = (t & 15) * 4, kl = t >> 4;
#pragma unroll
        for (int it = 0; it < 4; ++it) {
            int k = kl + it * 16;
            *(float4 *)&Ws[k][c4] = *(const float4 *)(W2 + k * 64 + c4);
        }
    }
    __syncthreads();

    int tc = t & 15, tr = t >> 4;
    int c0 = tc * 4, r0 = tr * 8;
    unsigned long long acc[4][4];
#pragma unroll
    for (int p = 0; p < 4; ++p)
#pragma unroll
        for (int j = 0; j < 4; ++j) acc[p][j] = 0ULL;

#pragma unroll 16
    for (int k = 0; k < 64; ++k) {
        ulonglong2 xa = *(const ulonglong2 *)&XsT[k][r0];
        ulonglong2 xb = *(const ulonglong2 *)&XsT[k][r0 + 4];
        float4 w = *(const float4 *)&Ws[k][c0];
        unsigned long long wd0 = bcast2(w.x), wd1 = bcast2(w.y);
        unsigned long long wd2 = bcast2(w.z), wd3 = bcast2(w.w);
        unsigned long long xp[4] = {xa.x, xa.y, xb.x, xb.y};
#pragma unroll
        for (int p = 0; p < 4; ++p) {
            fma2(acc[p][0], xp[p], wd0);
            fma2(acc[p][1], xp[p], wd1);
            fma2(acc[p][2], xp[p], wd2);
            fma2(acc[p][3], xp[p], wd3);
        }
    }

#pragma unroll
    for (int p = 0; p < 4; ++p) {
        int rA = rowbase + r0 + 2 * p;
#pragma unroll
        for (int j = 0; j < 4; ++j) {
            float lo, hi;
            unpack2(acc[p][j], lo, hi);
            int col = c0 + j;
            float b = bias2[col];
            if (rA < n)     out[rA * 64 + col] = lo + b;
            if (rA + 1 < n) out[(rA + 1) * 64 + col] = hi + b;
        }
    }
}

// ---------------------------------------------------------------------------
// Launcher
// Inputs (metadata order):
//  0 node_features [N,64] f32 | 1 edge_index [2,E] i32 | 2 edge_norm [E] f32 (UNUSED)
//  3 edge_type [E] i32 | 4 basis [30,64,64] f32 | 5 comp [8,30] f32
//  6 loop_weight [64,64] f32 | 7 bias1 [64] f32 | 8 weight2 [64,64] f32 | 9 bias2 [64]
// ---------------------------------------------------------------------------
extern "C" void kernel_launch(void *const *d_in, const int *in_sizes, int n_in,
                              void *d_out, int out_size) {
    const float *x     = (const float *)d_in[0];
    const int *ei      = (const int *)d_in[1];
    const int *et      = (const int *)d_in[3];
    const float *basis = (const float *)d_in[4];
    const float *comp  = (const float *)d_in[5];
    const float *loopw = (const float *)d_in[6];
    const float *bias1 = (const float *)d_in[7];
    const float *w2    = (const float *)d_in[8];
    const float *bias2 = (const float *)d_in[9];
    float *out = (float *)d_out;

    int n = in_sizes[0] / 64;
    int E = in_sizes[2];

    zero_deg_kernel<<<(n + 255) / 256, 256>>>(n);
    build_w_kernel<<<(64 * WCOLS + 255) / 256, 256>>>(basis, comp, loopw);
    deg_kernel<<<(E + 255) / 256, 256>>>(ei, E);

    gemm1_kernel<<<dim3((n + 127) / 128, 9), 256>>>(x, bias1, n);
    edge1_kernel<<<(E * 8 + 255) / 256, 256>>>(ei, et, E);

    hs_kernel<<<(n * 16 + 255) / 256, 256>>>(n);
    edge2_kernel<<<(E * 8 + 255) / 256, 256>>>(ei, E);

    gemm2_kernel<<<(n + 127) / 128, 256>>>(w2, bias2, out, n);
}

// round 4
// speedup vs baseline: 1.7010x; 1.7010x over previous
#include <cuda_runtime.h>

// ---------------------------------------------------------------------------
// N=50000 nodes, E=1000000 edges, R=8 relations, B=30 bases, DIN=H1=H2=64
// edge_index / edge_type are int32.
// ---------------------------------------------------------------------------
#define NMAX 50000
#define RCOLS 512            // 8 relations * 64
#define WCOLS 576            // + self-loop slice

__device__ __align__(16) float g_W[64 * WCOLS];
__device__ __align__(16) float g_xr[(long long)NMAX * RCOLS];
__device__ __align__(16) float g_agg1[NMAX * 64];
__device__ __align__(16) float g_hs[NMAX * 64];
__device__ __align__(16) float g_agg2[NMAX * 64];
__device__ float g_deg_out[NMAX];
__device__ float g_deg_in[NMAX];

// ---------------------------------------------------------------------------
// Packed f32x2 helpers
// ---------------------------------------------------------------------------
__device__ __forceinline__ void fma2(unsigned long long &d,
                                     unsigned long long a,
                                     unsigned long long b) {
    asm("fma.rn.f32x2 %0, %1, %2, %0;" : "+l"(d) : "l"(a), "l"(b));
}
__device__ __forceinline__ void add2(unsigned long long &d, unsigned long long b) {
    asm("add.rn.f32x2 %0, %0, %1;" : "+l"(d) : "l"(b));
}
__device__ __forceinline__ unsigned long long bcast2(float x) {
    unsigned long long r;
    unsigned u = __float_as_uint(x);
    asm("mov.b64 %0, {%1, %1};" : "=l"(r) : "r"(u));
    return r;
}
__device__ __forceinline__ void red4(float *p, float4 v) {
    asm volatile("red.global.add.v4.f32 [%0], {%1, %2, %3, %4};"
                 :: "l"(p), "f"(v.x), "f"(v.y), "f"(v.z), "f"(v.w) : "memory");
}

// ---------------------------------------------------------------------------
// Small kernels
// ---------------------------------------------------------------------------
__global__ void zero_deg_kernel(int n) {
    int i = blockIdx.x * blockDim.x + threadIdx.x;
    if (i < n) { g_deg_out[i] = 0.f; g_deg_in[i] = 0.f; }
}

__global__ void build_w_kernel(const float *__restrict__ basis,
                               const float *__restrict__ comp,
                               const float *__restrict__ loopw) {
    int id = blockIdx.x * blockDim.x + threadIdx.x;
    if (id >= 64 * WCOLS) return;
    int i = id / WCOLS, c = id % WCOLS;
    if (c < RCOLS) {
        int r = c >> 6, o = c & 63;
        float s = 0.f;
#pragma unroll
        for (int b = 0; b < 30; ++b)
            s += comp[r * 30 + b] * basis[b * 4096 + i * 64 + o];
        g_W[i * WCOLS + c] = s;
    } else {
        g_W[i * WCOLS + c] = loopw[i * 64 + (c - RCOLS)];
    }
}

// hs = agg1 * rsqrt(max(deg_out,1)); zero agg2 for next scatter
__global__ void hs_kernel(int n) {
    int idx = blockIdx.x * blockDim.x + threadIdx.x;
    if (idx >= n * 16) return;
    int node = idx >> 4, j = (idx & 15) * 4;
    float s = rsqrtf(fmaxf(g_deg_out[node], 1.f));
    float4 v = *(const float4 *)(g_agg1 + node * 64 + j);
    v.x *= s; v.y *= s; v.z *= s; v.w *= s;
    *(float4 *)(g_hs + node * 64 + j) = v;
    *(float4 *)(g_agg2 + node * 64 + j) = make_float4(0.f, 0.f, 0.f, 0.f);
}

// ---------------------------------------------------------------------------
// Edge scatter kernels: 8 threads per edge, 8 floats (2x float4) each.
// edge1 also accumulates degrees (merged deg pass).
// ---------------------------------------------------------------------------
__global__ void edge1_kernel(const int *__restrict__ ei,
                             const int *__restrict__ et, int E) {
    int idx = blockIdx.x * blockDim.x + threadIdx.x;
    int e = idx >> 3;
    if (e >= E) return;
    int part = idx & 7;
    int s = ei[e], d = ei[E + e], r = et[e];
    if (part == 0) {
        atomicAdd(&g_deg_out[s], 1.f);
        atomicAdd(&g_deg_in[d], 1.f);
    }
    const float4 *src = (const float4 *)(g_xr + (long long)s * RCOLS + r * 64 + part * 8);
    float *dst = g_agg1 + d * 64 + part * 8;
    red4(dst, src[0]);
    red4(dst + 4, src[1]);
}

__global__ void edge2_kernel(const int *__restrict__ ei, int E) {
    int idx = blockIdx.x * blockDim.x + threadIdx.x;
    int e = idx >> 3;
    if (e >= E) return;
    int part = idx & 7;
    int s = ei[e], d = ei[E + e];
    const float4 *src = (const float4 *)(g_hs + s * 64 + part * 8);
    float *dst = g_agg2 + d * 64 + part * 8;
    red4(dst, src[0]);
    red4(dst + 4, src[1]);
}

// ---------------------------------------------------------------------------
// GEMM 1: xr[N,576] = X[N,64] @ g_W[64,576]
// CTA: 128 threads, tile 128 rows x 64 cols, loops over 3 column tiles
// (grid.y=3 -> ctiles {3y,3y+1,3y+2}); X tile loaded/transposed ONCE per CTA.
// Thread tile: 8 rows x 8 cols, col-pair packed f32x2 accumulators ->
// per k: 4 LDS.128 + 8 bcast movs + 32 fma2  (FMA-pipe bound).
// ---------------------------------------------------------------------------
__global__ __launch_bounds__(128) void gemm1_kernel(const float *__restrict__ X,
                                                    const float *__restrict__ bias1,
                                                    int n) {
    __shared__ __align__(16) float XsT[64][128];   // [k][row]
    __shared__ __align__(16) float Ws[64][64];     // [k][col]
    int t = threadIdx.x;
    int rowbase = blockIdx.x * 128;

    {   // Each thread owns one row: 16 LDG.128, transposed STS (conflict-free:
        // 32 lanes store same k-row, 32 consecutive row-columns -> distinct banks)
        int row = rowbase + t;
        const float4 *xp = (const float4 *)(X + (long long)row * 64);
#pragma unroll
        for (int cg = 0; cg < 16; ++cg) {
            float4 v = (row < n) ? xp[cg] : make_float4(0.f, 0.f, 0.f, 0.f);
            XsT[cg * 4 + 0][t] = v.x;
            XsT[cg * 4 + 1][t] = v.y;
            XsT[cg * 4 + 2][t] = v.z;
            XsT[cg * 4 + 3][t] = v.w;
        }
    }

    int tc = t & 7, tr = t >> 3;
    int c0 = tc * 8, r0 = tr * 8;

    for (int ci = 0; ci < 3; ++ci) {
        int ct = blockIdx.y * 3 + ci;
        // Load W column tile: warp covers 128 contiguous smem floats -> no conflicts
#pragma unroll
        for (int j = 0; j < 8; ++j) {
            int s = t + j * 128;            // 0..1023 float4 slots
            int k = s >> 4, c4 = (s & 15) * 4;
            *(float4 *)&Ws[k][c4] =
                *(const float4 *)(g_W + k * WCOLS + ct * 64 + c4);
        }
        __syncthreads();

        unsigned long long acc[8][4];
#pragma unroll
        for (int r = 0; r < 8; ++r)
#pragma unroll
            for (int j = 0; j < 4; ++j) acc[r][j] = 0ULL;

#pragma unroll 8
        for (int k = 0; k < 64; ++k) {
            float4 xa = *(const float4 *)&XsT[k][r0];
            float4 xb = *(const float4 *)&XsT[k][r0 + 4];
            ulonglong2 wA = *(const ulonglong2 *)&Ws[k][c0];      // col pairs
            ulonglong2 wB = *(const ulonglong2 *)&Ws[k][c0 + 4];
            float xs[8] = {xa.x, xa.y, xa.z, xa.w, xb.x, xb.y, xb.z, xb.w};
#pragma unroll
            for (int r = 0; r < 8; ++r) {
                unsigned long long xd = bcast2(xs[r]);
                fma2(acc[r][0], xd, wA.x);
                fma2(acc[r][1], xd, wA.y);
                fma2(acc[r][2], xd, wB.x);
                fma2(acc[r][3], xd, wB.y);
            }
        }

        if (ct < 8) {
#pragma unroll
            for (int r = 0; r < 8; ++r) {
                int grow = rowbase + r0 + r;
                if (grow < n) {
                    float *p = g_xr + (long long)grow * RCOLS + ct * 64 + c0;
                    *(ulonglong2 *)p       = make_ulonglong2(acc[r][0], acc[r][1]);
                    *(ulonglong2 *)(p + 4) = make_ulonglong2(acc[r][2], acc[r][3]);
                }
            }
        } else {  // self-loop slice: agg1 = loop term + bias1
            ulonglong2 bA = *(const ulonglong2 *)(bias1 + c0);
            ulonglong2 bB = *(const ulonglong2 *)(bias1 + c0 + 4);
#pragma unroll
            for (int r = 0; r < 8; ++r) {
                add2(acc[r][0], bA.x); add2(acc[r][1], bA.y);
                add2(acc[r][2], bB.x); add2(acc[r][3], bB.y);
                int grow = rowbase + r0 + r;
                if (grow < n) {
                    float *p = g_agg1 + grow * 64 + c0;
                    *(ulonglong2 *)p       = make_ulonglong2(acc[r][0], acc[r][1]);
                    *(ulonglong2 *)(p + 4) = make_ulonglong2(acc[r][2], acc[r][3]);
                }
            }
        }
        __syncthreads();   // Ws WAR before next column tile
    }
}

// ---------------------------------------------------------------------------
// GEMM 2: out[N,64] = (agg2 * rsqrt(max(deg_in,1))) @ W2 + bias2
// Same structure, single column tile.
// ---------------------------------------------------------------------------
__global__ __launch_bounds__(128) void gemm2_kernel(const float *__restrict__ W2,
                                                    const float *__restrict__ bias2,
                                                    float *__restrict__ out,
                                                    int n) {
    __shared__ __align__(16) float XsT[64][128];
    __shared__ __align__(16) float Ws[64][64];
    int t = threadIdx.x;
    int rowbase = blockIdx.x * 128;

    {
        int row = rowbase + t;
        float sc = 0.f;
        const float4 *xp = (const float4 *)(g_agg2 + (long long)row * 64);
        if (row < n) sc = rsqrtf(fmaxf(g_deg_in[row], 1.f));
#pragma unroll
        for (int cg = 0; cg < 16; ++cg) {
            float4 v = (row < n) ? xp[cg] : make_float4(0.f, 0.f, 0.f, 0.f);
            XsT[cg * 4 + 0][t] = v.x * sc;
            XsT[cg * 4 + 1][t] = v.y * sc;
            XsT[cg * 4 + 2][t] = v.z * sc;
            XsT[cg * 4 + 3][t] = v.w * sc;
        }
    }
#pragma unroll
    for (int j = 0; j < 8; ++j) {
        int s = t + j * 128;
        int k = s >> 4, c4 = (s & 15) * 4;
        *(float4 *)&Ws[k][c4] = *(const float4 *)(W2 + k * 64 + c4);
    }
    __syncthreads();

    int tc = t & 7, tr = t >> 3;
    int c0 = tc * 8, r0 = tr * 8;

    unsigned long long acc[8][4];
#pragma unroll
    for (int r = 0; r < 8; ++r)
#pragma unroll
        for (int j = 0; j < 4; ++j) acc[r][j] = 0ULL;

#pragma unroll 8
    for (int k = 0; k < 64; ++k) {
        float4 xa = *(const float4 *)&XsT[k][r0];
        float4 xb = *(const float4 *)&XsT[k][r0 + 4];
        ulonglong2 wA = *(const ulonglong2 *)&Ws[k][c0];
        ulonglong2 wB = *(const ulonglong2 *)&Ws[k][c0 + 4];
        float xs[8] = {xa.x, xa.y, xa.z, xa.w, xb.x, xb.y, xb.z, xb.w};
#pragma unroll
        for (int r = 0; r < 8; ++r) {
            unsigned long long xd = bcast2(xs[r]);
            fma2(acc[r][0], xd, wA.x);
            fma2(acc[r][1], xd, wA.y);
            fma2(acc[r][2], xd, wB.x);
            fma2(acc[r][3], xd, wB.y);
        }
    }

    ulonglong2 bA = *(const ulonglong2 *)(bias2 + c0);
    ulonglong2 bB = *(const ulonglong2 *)(bias2 + c0 + 4);
#pragma unroll
    for (int r = 0; r < 8; ++r) {
        add2(acc[r][0], bA.x); add2(acc[r][1], bA.y);
        add2(acc[r][2], bB.x); add2(acc[r][3], bB.y);
        int grow = rowbase + r0 + r;
        if (grow < n) {
            float *p = out + grow * 64 + c0;
            *(ulonglong2 *)p       = make_ulonglong2(acc[r][0], acc[r][1]);
            *(ulonglong2 *)(p + 4) = make_ulonglong2(acc[r][2], acc[r][3]);
        }
    }
}

// ---------------------------------------------------------------------------
// Launcher.  Inputs (metadata order):
//  0 node_features [N,64] f32 | 1 edge_index [2,E] i32 | 2 edge_norm [E] f32 (UNUSED)
//  3 edge_type [E] i32 | 4 basis [30,64,64] f32 | 5 comp [8,30] f32
//  6 loop_weight [64,64] f32 | 7 bias1 [64] f32 | 8 weight2 [64,64] f32 | 9 bias2 [64]
// ---------------------------------------------------------------------------
extern "C" void kernel_launch(void *const *d_in, const int *in_sizes, int n_in,
                              void *d_out, int out_size) {
    const float *x     = (const float *)d_in[0];
    const int *ei      = (const int *)d_in[1];
    const int *et      = (const int *)d_in[3];
    const float *basis = (const float *)d_in[4];
    const float *comp  = (const float *)d_in[5];
    const float *loopw = (const float *)d_in[6];
    const float *bias1 = (const float *)d_in[7];
    const float *w2    = (const float *)d_in[8];
    const float *bias2 = (const float *)d_in[9];
    float *out = (float *)d_out;

    int n = in_sizes[0] / 64;
    int E = in_sizes[2];
    int rb = (n + 127) / 128;

    zero_deg_kernel<<<(n + 255) / 256, 256>>>(n);
    build_w_kernel<<<(64 * WCOLS + 255) / 256, 256>>>(basis, comp, loopw);

    gemm1_kernel<<<dim3(rb, 3), 128>>>(x, bias1, n);
    edge1_kernel<<<(E * 8 + 255) / 256, 256>>>(ei, et, E);

    hs_kernel<<<(n * 16 + 255) / 256, 256>>>(n);
    edge2_kernel<<<(E * 8 + 255) / 256, 256>>>(ei, E);

    gemm2_kernel<<<rb, 128>>>(w2, bias2, out, n);
}

// round 6
// speedup vs baseline: 1.8658x; 1.0969x over previous
#include <cuda_runtime.h>

// ---------------------------------------------------------------------------
// N=50000 nodes, E=1000000 edges, R=8 relations, B=30 bases, DIN=H1=H2=64
// edge_index / edge_type are int32.
//
// Restructure: agg1[d] = sum_r W_r^T * (sum_{e:dst=d,rel=r} x[src_e]) + loop + b
//   -> CSR keyed by (dst*8+rel), aggregate raw x into S[N,512], then one
//      K=576 GEMM over [S | x]. No atomics in the hot paths.
// ---------------------------------------------------------------------------
#define NMAX 50000
#define EMAX 1000000
#define NSEG (NMAX * 8)          // 400000 (dst,rel) keys
#define SCAN_BLK 1024
#define NBLK ((NSEG + SCAN_BLK - 1) / SCAN_BLK)   // 391

__device__ __align__(16) float g_Wc[576 * 64];   // [k=r*64+i | 512+i][o]
__device__ __align__(16) float g_S[(long long)NMAX * 512];  // per-(d,r) sums
__device__ __align__(16) float g_agg1[NMAX * 64];
__device__ __align__(16) float g_hs[NMAX * 64];
__device__ __align__(16) float g_agg2[NMAX * 64];
__device__ int g_hist[NSEG];
__device__ int g_scan[NSEG];
__device__ int g_rowptr[NSEG + 1];
__device__ int g_cursor[NSEG];
__device__ int g_blocksums[NBLK];
__device__ int g_blockoff[NBLK];
__device__ int g_csr_src[EMAX];
__device__ int g_dego[NMAX];

// ---------------------------------------------------------------------------
// Packed f32x2 helpers
// ---------------------------------------------------------------------------
__device__ __forceinline__ void fma2(unsigned long long &d,
                                     unsigned long long a,
                                     unsigned long long b) {
    asm("fma.rn.f32x2 %0, %1, %2, %0;" : "+l"(d) : "l"(a), "l"(b));
}
__device__ __forceinline__ void add2(unsigned long long &d, unsigned long long b) {
    asm("add.rn.f32x2 %0, %0, %1;" : "+l"(d) : "l"(b));
}
__device__ __forceinline__ unsigned long long bcast2(float x) {
    unsigned long long r;
    unsigned u = __float_as_uint(x);
    asm("mov.b64 %0, {%1, %1};" : "=l"(r) : "r"(u));
    return r;
}

// ---------------------------------------------------------------------------
// CSR build
// ---------------------------------------------------------------------------
__global__ void zero_kernel() {
    int i = blockIdx.x * blockDim.x + threadIdx.x;
    if (i < NSEG) g_hist[i] = 0;
    if (i < NMAX) g_dego[i] = 0;
}

__global__ void hist_kernel(const int *__restrict__ ei,
                            const int *__restrict__ et, int E) {
    int e = blockIdx.x * blockDim.x + threadIdx.x;
    if (e >= E) return;
    int s = ei[e], d = ei[E + e], r = et[e];
    atomicAdd(&g_hist[d * 8 + r], 1);
    atomicAdd(&g_dego[s], 1);
}

__global__ void scan_block_kernel() {
    __shared__ int sh[SCAN_BLK];
    int t = threadIdx.x;
    int i = blockIdx.x * SCAN_BLK + t;
    int v = (i < NSEG) ? g_hist[i] : 0;
    sh[t] = v;
    __syncthreads();
#pragma unroll
    for (int off = 1; off < SCAN_BLK; off <<= 1) {
        int add = (t >= off) ? sh[t - off] : 0;
        __syncthreads();
        sh[t] += add;
        __syncthreads();
    }
    if (i < NSEG) g_scan[i] = sh[t];            // inclusive within block
    if (t == SCAN_BLK - 1) g_blocksums[blockIdx.x] = sh[t];
}

__global__ void scan_top_kernel() {             // one block, 512 threads
    __shared__ int sh[512];
    int t = threadIdx.x;
    int v = (t < NBLK) ? g_blocksums[t] : 0;
    sh[t] = v;
    __syncthreads();
#pragma unroll
    for (int off = 1; off < 512; off <<= 1) {
        int add = (t >= off) ? sh[t - off] : 0;
        __syncthreads();
        sh[t] += add;
        __syncthreads();
    }
    if (t < NBLK) g_blockoff[t] = sh[t] - v;    // exclusive block offsets
}

__global__ void scan_add_kernel(int E) {
    int i = blockIdx.x * SCAN_BLK + threadIdx.x;
    if (i < NSEG) {
        int excl = g_scan[i] - g_hist[i] + g_blockoff[i >> 10];
        g_rowptr[i] = excl;
        g_cursor[i] = excl;
    }
    if (i == 0) g_rowptr[NSEG] = E;
}

__global__ void fill_kernel(const int *__restrict__ ei,
                            const int *__restrict__ et, int E) {
    int e = blockIdx.x * blockDim.x + threadIdx.x;
    if (e >= E) return;
    int s = ei[e], d = ei[E + e], r = et[e];
    int pos = atomicAdd(&g_cursor[d * 8 + r], 1);
    g_csr_src[pos] = s;
}

// ---------------------------------------------------------------------------
// Phase A: S[seg][64] = sum over segment of x[src]  (8 threads per segment)
// Gathers hit the 12.8MB L2-hot x; no atomics; empty segments store zeros.
// ---------------------------------------------------------------------------
__global__ void seg_agg_kernel(const float *__restrict__ X) {
    int idx = blockIdx.x * blockDim.x + threadIdx.x;
    int seg = idx >> 3;
    if (seg >= NSEG) return;
    int lane = idx & 7;
    int lo = g_rowptr[seg], hi = g_rowptr[seg + 1];
    float4 a0 = make_float4(0.f, 0.f, 0.f, 0.f);
    float4 a1 = make_float4(0.f, 0.f, 0.f, 0.f);
    for (int i = lo; i < hi; ++i) {
        int s = g_csr_src[i];                   // broadcast within group
        const float4 *p = (const float4 *)(X + s * 64 + lane * 8);
        float4 v0 = p[0], v1 = p[1];
        a0.x += v0.x; a0.y += v0.y; a0.z += v0.z; a0.w += v0.w;
        a1.x += v1.x; a1.y += v1.y; a1.z += v1.z; a1.w += v1.w;
    }
    float4 *q = (float4 *)(g_S + (long long)seg * 64 + lane * 8);
    q[0] = a0; q[1] = a1;
}

// ---------------------------------------------------------------------------
// Weight build: g_Wc[(r*64+i)*64+o] = sum_b comp[r,b]*basis[b,i,o];
//               g_Wc[(512+i)*64+o]  = loop[i][o]
// ---------------------------------------------------------------------------
__global__ void build_w_kernel(const float *__restrict__ basis,
                               const float *__restrict__ comp,
                               const float *__restrict__ loopw) {
    int id = blockIdx.x * blockDim.x + threadIdx.x;
    if (id >= 576 * 64) return;
    int k = id >> 6, o = id & 63;
    if (k < 512) {
        int r = k >> 6, i = k & 63;
        float s = 0.f;
#pragma unroll
        for (int b = 0; b < 30; ++b)
            s += comp[r * 30 + b] * basis[b * 4096 + i * 64 + o];
        g_Wc[id] = s;
    } else {
        g_Wc[id] = loopw[(k - 512) * 64 + o];
    }
}

// hs = agg1 * rsqrt(max(deg_out,1))
__global__ void hs_kernel(int n) {
    int idx = blockIdx.x * blockDim.x + threadIdx.x;
    if (idx >= n * 16) return;
    int node = idx >> 4, j = (idx & 15) * 4;
    float s = rsqrtf(fmaxf((float)g_dego[node], 1.f));
    float4 v = *(const float4 *)(g_agg1 + node * 64 + j);
    v.x *= s; v.y *= s; v.z *= s; v.w *= s;
    *(float4 *)(g_hs + node * 64 + j) = v;
}

// ---------------------------------------------------------------------------
// Layer-2 aggregation via CSR: agg2[d] = sum over dst-row of hs[src].
// dst-row d = segments [8d, 8d+8) -> contiguous [rowptr[8d], rowptr[8d+8]).
// ---------------------------------------------------------------------------
__global__ void row_agg2_kernel(int n) {
    int idx = blockIdx.x * blockDim.x + threadIdx.x;
    int d = idx >> 3;
    if (d >= n) return;
    int lane = idx & 7;
    int lo = g_rowptr[d * 8], hi = g_rowptr[d * 8 + 8];
    float4 a0 = make_float4(0.f, 0.f, 0.f, 0.f);
    float4 a1 = make_float4(0.f, 0.f, 0.f, 0.f);
    for (int i = lo; i < hi; ++i) {
        int s = g_csr_src[i];
        const float4 *p = (const float4 *)(g_hs + s * 64 + lane * 8);
        float4 v0 = p[0], v1 = p[1];
        a0.x += v0.x; a0.y += v0.y; a0.z += v0.z; a0.w += v0.w;
        a1.x += v1.x; a1.y += v1.y; a1.z += v1.z; a1.w += v1.w;
    }
    float4 *q = (float4 *)(g_agg2 + d * 64 + lane * 8);
    q[0] = a0; q[1] = a1;
}

// ---------------------------------------------------------------------------
// GEMM A: agg1[N,64] = [S | x][N,576] @ g_Wc[576,64] + bias1
// CTA 128 threads, 128 rows, K loop = 9 tiles of 64. Thread tile 8x8,
// col-pair f32x2 accumulators.
// ---------------------------------------------------------------------------
__global__ __launch_bounds__(128) void gemmA_kernel(const float *__restrict__ X,
                                                    const float *__restrict__ bias1,
                                                    int n) {
    __shared__ __align__(16) float XsT[64][128];
    __shared__ __align__(16) float Ws[64][64];
    int t = threadIdx.x;
    int rowbase = blockIdx.x * 128;
    int row = rowbase + t;
    int tc = t & 7, tr = t >> 3;
    int c0 = tc * 8, r0 = tr * 8;

    unsigned long long acc[8][4];
#pragma unroll
    for (int r = 0; r < 8; ++r)
#pragma unroll
        for (int j = 0; j < 4; ++j) acc[r][j] = 0ULL;

    for (int kt = 0; kt < 9; ++kt) {
        // load input k-tile (row-per-thread, transposed store)
        const float4 *xp = (kt < 8)
            ? (const float4 *)(g_S + (long long)row * 512 + kt * 64)
            : (const float4 *)(X + (long long)row * 64);
#pragma unroll
        for (int cg = 0; cg < 16; ++cg) {
            float4 v = (row < n) ? xp[cg] : make_float4(0.f, 0.f, 0.f, 0.f);
            XsT[cg * 4 + 0][t] = v.x;
            XsT[cg * 4 + 1][t] = v.y;
            XsT[cg * 4 + 2][t] = v.z;
            XsT[cg * 4 + 3][t] = v.w;
        }
        // load W k-tile
#pragma unroll
        for (int j = 0; j < 8; ++j) {
            int s = t + j * 128;
            int k = s >> 4, c4 = (s & 15) * 4;
            *(float4 *)&Ws[k][c4] =
                *(const float4 *)(g_Wc + (kt * 64 + k) * 64 + c4);
        }
        __syncthreads();

#pragma unroll 8
        for (int k = 0; k < 64; ++k) {
            float4 xa = *(const float4 *)&XsT[k][r0];
            float4 xb = *(const float4 *)&XsT[k][r0 + 4];
            ulonglong2 wA = *(const ulonglong2 *)&Ws[k][c0];
            ulonglong2 wB = *(const ulonglong2 *)&Ws[k][c0 + 4];
            float xs[8] = {xa.x, xa.y, xa.z, xa.w, xb.x, xb.y, xb.z, xb.w};
#pragma unroll
            for (int r = 0; r < 8; ++r) {
                unsigned long long xd = bcast2(xs[r]);
                fma2(acc[r][0], xd, wA.x);
                fma2(acc[r][1], xd, wA.y);
                fma2(acc[r][2], xd, wB.x);
                fma2(acc[r][3], xd, wB.y);
            }
        }
        __syncthreads();
    }

    ulonglong2 bA = *(const ulonglong2 *)(bias1 + c0);
    ulonglong2 bB = *(const ulonglong2 *)(bias1 + c0 + 4);
#pragma unroll
    for (int r = 0; r < 8; ++r) {
        add2(acc[r][0], bA.x); add2(acc[r][1], bA.y);
        add2(acc[r][2], bB.x); add2(acc[r][3], bB.y);
        int grow = rowbase + r0 + r;
        if (grow < n) {
            float *p = g_agg1 + grow * 64 + c0;
            *(ulonglong2 *)p       = make_ulonglong2(acc[r][0], acc[r][1]);
            *(ulonglong2 *)(p + 4) = make_ulonglong2(acc[r][2], acc[r][3]);
        }
    }
}

// ---------------------------------------------------------------------------
// GEMM 2: out[N,64] = (agg2 * rsqrt(max(deg_in,1))) @ W2 + bias2
// deg_in derived from rowptr (free).
// ---------------------------------------------------------------------------
__global__ __launch_bounds__(128) void gemm2_kernel(const float *__restrict__ W2,
                                                    const float *__restrict__ bias2,
                                                    float *__restrict__ out,
                                                    int n) {
    __shared__ __align__(16) float XsT[64][128];
    __shared__ __align__(16) float Ws[64][64];
    int t = threadIdx.x;
    int rowbase = blockIdx.x * 128;

    {
        int row = rowbase + t;
        float sc = 0.f;
        const float4 *xp = (const float4 *)(g_agg2 + (long long)row * 64);
        if (row < n) {
            float deg = (float)(g_rowptr[row * 8 + 8] - g_rowptr[row * 8]);
            sc = rsqrtf(fmaxf(deg, 1.f));
        }
#pragma unroll
        for (int cg = 0; cg < 16; ++cg) {
            float4 v = (row < n) ? xp[cg] : make_float4(0.f, 0.f, 0.f, 0.f);
            XsT[cg * 4 + 0][t] = v.x * sc;
            XsT[cg * 4 + 1][t] = v.y * sc;
            XsT[cg * 4 + 2][t] = v.z * sc;
            XsT[cg * 4 + 3][t] = v.w * sc;
        }
    }
#pragma unroll
    for (int j = 0; j < 8; ++j) {
        int s = t + j * 128;
        int k = s >> 4, c4 = (s & 15) * 4;
        *(float4 *)&Ws[k][c4] = *(const float4 *)(W2 + k * 64 + c4);
    }
    __syncthreads();

    int tc = t & 7, tr = t >> 3;
    int c0 = tc * 8, r0 = tr * 8;

    unsigned long long acc[8][4];
#pragma unroll
    for (int r = 0; r < 8; ++r)
#pragma unroll
        for (int j = 0; j < 4; ++j) acc[r][j] = 0ULL;

#pragma unroll 8
    for (int k = 0; k < 64; ++k) {
        float4 xa = *(const float4 *)&XsT[k][r0];
        float4 xb = *(const float4 *)&XsT[k][r0 + 4];
        ulonglong2 wA = *(const ulonglong2 *)&Ws[k][c0];
        ulonglong2 wB = *(const ulonglong2 *)&Ws[k][c0 + 4];
        float xs[8] = {xa.x, xa.y, xa.z, xa.w, xb.x, xb.y, xb.z, xb.w};
#pragma unroll
        for (int r = 0; r < 8; ++r) {
            unsigned long long xd = bcast2(xs[r]);
            fma2(acc[r][0], xd, wA.x);
            fma2(acc[r][1], xd, wA.y);
            fma2(acc[r][2], xd, wB.x);
            fma2(acc[r][3], xd, wB.y);
        }
    }

    ulonglong2 bA = *(const ulonglong2 *)(bias2 + c0);
    ulonglong2 bB = *(const ulonglong2 *)(bias2 + c0 + 4);
#pragma unroll
    for (int r = 0; r < 8; ++r) {
        add2(acc[r][0], bA.x); add2(acc[r][1], bA.y);
        add2(acc[r][2], bB.x); add2(acc[r][3], bB.y);
        int grow = rowbase + r0 + r;
        if (grow < n) {
            float *p = out + grow * 64 + c0;
            *(ulonglong2 *)p       = make_ulonglong2(acc[r][0], acc[r][1]);
            *(ulonglong2 *)(p + 4) = make_ulonglong2(acc[r][2], acc[r][3]);
        }
    }
}

// ---------------------------------------------------------------------------
// Launcher.  Inputs (metadata order):
//  0 node_features [N,64] f32 | 1 edge_index [2,E] i32 | 2 edge_norm (UNUSED)
//  3 edge_type [E] i32 | 4 basis [30,64,64] | 5 comp [8,30]
//  6 loop_weight [64,64] | 7 bias1 [64] | 8 weight2 [64,64] | 9 bias2 [64]
// ---------------------------------------------------------------------------
extern "C" void kernel_launch(void *const *d_in, const int *in_sizes, int n_in,
                              void *d_out, int out_size) {
    const float *x     = (const float *)d_in[0];
    const int *ei      = (const int *)d_in[1];
    const int *et      = (const int *)d_in[3];
    const float *basis = (const float *)d_in[4];
    const float *comp  = (const float *)d_in[5];
    const float *loopw = (const float *)d_in[6];
    const float *bias1 = (const float *)d_in[7];
    const float *w2    = (const float *)d_in[8];
    const float *bias2 = (const float *)d_in[9];
    float *out = (float *)d_out;

    int n = in_sizes[0] / 64;
    int E = in_sizes[2];
    int rb = (n + 127) / 128;

    zero_kernel<<<(NSEG + 255) / 256, 256>>>();
    build_w_kernel<<<(576 * 64 + 255) / 256, 256>>>(basis, comp, loopw);
    hist_kernel<<<(E + 255) / 256, 256>>>(ei, et, E);

    scan_block_kernel<<<NBLK, SCAN_BLK>>>();
    scan_top_kernel<<<1, 512>>>();
    scan_add_kernel<<<NBLK, SCAN_BLK>>>(E);
    fill_kernel<<<(E + 255) / 256, 256>>>(ei, et, E);

    seg_agg_kernel<<<(NSEG * 8 + 255) / 256, 256>>>(x);
    gemmA_kernel<<<rb, 128>>>(x, bias1, n);

    hs_kernel<<<(n * 16 + 255) / 256, 256>>>(n);
    row_agg2_kernel<<<(n * 8 + 255) / 256, 256>>>(n);
    gemm2_kernel<<<rb, 128>>>(w2, bias2, out, n);
}

// round 7
// speedup vs baseline: 2.0745x; 1.1118x over previous
#include <cuda_runtime.h>
#include <cuda_fp16.h>

// ---------------------------------------------------------------------------
// N=50000 nodes, E=1000000 edges, R=8 relations, B=30 bases, DIN=H1=H2=64
// edge_index / edge_type are int32.
//
// agg1[d] = sum_r W_r^T * (sum_{e:dst=d,rel=r} x[src_e]) + loop + bias
//   -> CSR keyed by (dst*8+rel); aggregate raw x into S[N,512] (fp16),
//      then one K=576 GEMM over [S | x] with fused rsqrt(deg_out) epilogue
//      writing hs directly. Layer 2 = CSR row gather + small GEMM.
// ---------------------------------------------------------------------------
#define NMAX 50000
#define EMAX 1000000
#define NSEG (NMAX * 8)
#define SCAN_BLK 1024
#define NBLK ((NSEG + SCAN_BLK - 1) / SCAN_BLK)   // 391

__device__ __align__(16) float   g_Wc[576 * 64];
__device__ __align__(16) __half2 g_Sh[(long long)NMAX * 256];  // [N][512] fp16
__device__ __align__(16) float   g_hs[NMAX * 64];
__device__ __align__(16) float   g_agg2[NMAX * 64];
__device__ int g_hist[NSEG];
__device__ int g_scan[NSEG];
__device__ int g_rowptr[NSEG + 1];
__device__ int g_cursor[NSEG];
__device__ int g_blocksums[NBLK];
__device__ int g_blockoff[NBLK];
__device__ int g_csr_src[EMAX];
__device__ int g_dego[NMAX];

// ---------------------------------------------------------------------------
// Packed f32x2 helpers
// ---------------------------------------------------------------------------
__device__ __forceinline__ void fma2(unsigned long long &d,
                                     unsigned long long a,
                                     unsigned long long b) {
    asm("fma.rn.f32x2 %0, %1, %2, %0;" : "+l"(d) : "l"(a), "l"(b));
}
__device__ __forceinline__ void add2(unsigned long long &d, unsigned long long b) {
    asm("add.rn.f32x2 %0, %0, %1;" : "+l"(d) : "l"(b));
}
__device__ __forceinline__ void mul2(unsigned long long &d, unsigned long long b) {
    asm("mul.rn.f32x2 %0, %0, %1;" : "+l"(d) : "l"(b));
}
__device__ __forceinline__ unsigned long long bcast2(float x) {
    unsigned long long r;
    unsigned u = __float_as_uint(x);
    asm("mov.b64 %0, {%1, %1};" : "=l"(r) : "r"(u));
    return r;
}

__device__ __forceinline__ int warp_incl_scan(int x, int lane) {
#pragma unroll
    for (int off = 1; off < 32; off <<= 1) {
        int y = __shfl_up_sync(0xffffffffu, x, off);
        if (lane >= off) x += y;
    }
    return x;
}

// ---------------------------------------------------------------------------
// CSR build
// ---------------------------------------------------------------------------
__global__ void zero_kernel() {
    int i = blockIdx.x * blockDim.x + threadIdx.x;
    if (i < NSEG) g_hist[i] = 0;
    if (i < NMAX) g_dego[i] = 0;
}

__global__ void hist_kernel(const int *__restrict__ ei,
                            const int *__restrict__ et, int E) {
    int e = blockIdx.x * blockDim.x + threadIdx.x;
    if (e >= E) return;
    int s = ei[e], d = ei[E + e], r = et[e];
    atomicAdd(&g_hist[d * 8 + r], 1);
    atomicAdd(&g_dego[s], 1);
}

__global__ void scan_block_kernel() {
    __shared__ int ws[32];
    int t = threadIdx.x, i = blockIdx.x * SCAN_BLK + t;
    int v = (i < NSEG) ? g_hist[i] : 0;
    int lane = t & 31, w = t >> 5;
    int x = warp_incl_scan(v, lane);
    if (lane == 31) ws[w] = x;
    __syncthreads();
    if (w == 0) {
        int y = ws[lane];
        y = warp_incl_scan(y, lane);
        ws[lane] = y;
    }
    __syncthreads();
    int incl = x + (w ? ws[w - 1] : 0);
    if (i < NSEG) g_scan[i] = incl;
    if (t == SCAN_BLK - 1) g_blocksums[blockIdx.x] = incl;
}

__global__ void scan_top_kernel() {             // one block, 512 threads
    __shared__ int ws[16];
    int t = threadIdx.x, lane = t & 31, w = t >> 5;
    int v = (t < NBLK) ? g_blocksums[t] : 0;
    int x = warp_incl_scan(v, lane);
    if (lane == 31) ws[w] = x;
    __syncthreads();
    if (w == 0) {
        int y = (lane < 16) ? ws[lane] : 0;
        y = warp_incl_scan(y, lane);
        if (lane < 16) ws[lane] = y;
    }
    __syncthreads();
    int incl = x + (w ? ws[w - 1] : 0);
    if (t < NBLK) g_blockoff[t] = incl - v;     // exclusive
}

__global__ void scan_add_kernel(int E) {
    int i = blockIdx.x * SCAN_BLK + threadIdx.x;
    if (i < NSEG) {
        int excl = g_scan[i] - g_hist[i] + g_blockoff[i >> 10];
        g_rowptr[i] = excl;
        g_cursor[i] = excl;
    }
    if (i == 0) g_rowptr[NSEG] = E;
}

__global__ void fill_kernel(const int *__restrict__ ei,
                            const int *__restrict__ et, int E) {
    int e = blockIdx.x * blockDim.x + threadIdx.x;
    if (e >= E) return;
    int s = ei[e], d = ei[E + e], r = et[e];
    int pos = atomicAdd(&g_cursor[d * 8 + r], 1);
    g_csr_src[pos] = s;
}

// ---------------------------------------------------------------------------
// Phase A: S[seg][64] = fp16(sum over segment of x[src])  (8 threads/segment)
// ---------------------------------------------------------------------------
__global__ void seg_agg_kernel(const float *__restrict__ X) {
    int idx = blockIdx.x * blockDim.x + threadIdx.x;
    int seg = idx >> 3;
    if (seg >= NSEG) return;
    int lane = idx & 7;
    int lo = g_rowptr[seg], hi = g_rowptr[seg + 1];
    float4 a0 = make_float4(0.f, 0.f, 0.f, 0.f);
    float4 a1 = make_float4(0.f, 0.f, 0.f, 0.f);
    int i = lo;
    for (; i + 1 < hi; i += 2) {                // 2x unroll for MLP
        int s0 = g_csr_src[i], s1 = g_csr_src[i + 1];
        const float4 *p0 = (const float4 *)(X + s0 * 64 + lane * 8);
        const float4 *p1 = (const float4 *)(X + s1 * 64 + lane * 8);
        float4 u0 = p0[0], u1 = p0[1], v0 = p1[0], v1 = p1[1];
        a0.x += u0.x + v0.x; a0.y += u0.y + v0.y;
        a0.z += u0.z + v0.z; a0.w += u0.w + v0.w;
        a1.x += u1.x + v1.x; a1.y += u1.y + v1.y;
        a1.z += u1.z + v1.z; a1.w += u1.w + v1.w;
    }
    if (i < hi) {
        int s = g_csr_src[i];
        const float4 *p = (const float4 *)(X + s * 64 + lane * 8);
        float4 u0 = p[0], u1 = p[1];
        a0.x += u0.x; a0.y += u0.y; a0.z += u0.z; a0.w += u0.w;
        a1.x += u1.x; a1.y += u1.y; a1.z += u1.z; a1.w += u1.w;
    }
    __half2 h0 = __floats2half2_rn(a0.x, a0.y);
    __half2 h1 = __floats2half2_rn(a0.z, a0.w);
    __half2 h2 = __floats2half2_rn(a1.x, a1.y);
    __half2 h3 = __floats2half2_rn(a1.z, a1.w);
    uint4 u;
    u.x = *(unsigned *)&h0; u.y = *(unsigned *)&h1;
    u.z = *(unsigned *)&h2; u.w = *(unsigned *)&h3;
    *(uint4 *)(g_Sh + (long long)seg * 32 + lane * 4) = u;
}

// ---------------------------------------------------------------------------
// Weight build
// ---------------------------------------------------------------------------
__global__ void build_w_kernel(const float *__restrict__ basis,
                               const float *__restrict__ comp,
                               const float *__restrict__ loopw) {
    int id = blockIdx.x * blockDim.x + threadIdx.x;
    if (id >= 576 * 64) return;
    int k = id >> 6, o = id & 63;
    if (k < 512) {
        int r = k >> 6, i = k & 63;
        float s = 0.f;
#pragma unroll
        for (int b = 0; b < 30; ++b)
            s += comp[r * 30 + b] * basis[b * 4096 + i * 64 + o];
        g_Wc[id] = s;
    } else {
        g_Wc[id] = loopw[(k - 512) * 64 + o];
    }
}

// ---------------------------------------------------------------------------
// GEMM A: hs[N,64] = ([S | x][N,576] @ g_Wc[576,64] + bias1) * rsqrt(deg_out)
// ---------------------------------------------------------------------------
__global__ __launch_bounds__(128) void gemmA_kernel(const float *__restrict__ X,
                                                    const float *__restrict__ bias1,
                                                    int n) {
    __shared__ __align__(16) float XsT[64][128];
    __shared__ __align__(16) float Ws[64][64];
    int t = threadIdx.x;
    int rowbase = blockIdx.x * 128;
    int row = rowbase + t;
    int tc = t & 7, tr = t >> 3;
    int c0 = tc * 8, r0 = tr * 8;

    unsigned long long acc[8][4];
#pragma unroll
    for (int r = 0; r < 8; ++r)
#pragma unroll
        for (int j = 0; j < 4; ++j) acc[r][j] = 0ULL;

    for (int kt = 0; kt < 9; ++kt) {
        if (kt < 8) {   // fp16 S tile
            const uint4 *sp = (const uint4 *)(g_Sh + ((long long)row * 256 + kt * 32));
#pragma unroll
            for (int g = 0; g < 8; ++g) {
                float f0=0.f,f1=0.f,f2=0.f,f3=0.f,f4=0.f,f5=0.f,f6=0.f,f7=0.f;
                if (row < n) {
                    uint4 u = sp[g];
                    float2 a = __half22float2(*(__half2 *)&u.x);
                    float2 b = __half22float2(*(__half2 *)&u.y);
                    float2 c = __half22float2(*(__half2 *)&u.z);
                    float2 d = __half22float2(*(__half2 *)&u.w);
                    f0=a.x; f1=a.y; f2=b.x; f3=b.y; f4=c.x; f5=c.y; f6=d.x; f7=d.y;
                }
                XsT[g * 8 + 0][t] = f0; XsT[g * 8 + 1][t] = f1;
                XsT[g * 8 + 2][t] = f2; XsT[g * 8 + 3][t] = f3;
                XsT[g * 8 + 4][t] = f4; XsT[g * 8 + 5][t] = f5;
                XsT[g * 8 + 6][t] = f6; XsT[g * 8 + 7][t] = f7;
            }
        } else {        // fp32 x tile
            const float4 *xp = (const float4 *)(X + (long long)row * 64);
#pragma unroll
            for (int cg = 0; cg < 16; ++cg) {
                float4 v = (row < n) ? xp[cg] : make_float4(0.f, 0.f, 0.f, 0.f);
                XsT[cg * 4 + 0][t] = v.x;
                XsT[cg * 4 + 1][t] = v.y;
                XsT[cg * 4 + 2][t] = v.z;
                XsT[cg * 4 + 3][t] = v.w;
            }
        }
#pragma unroll
        for (int j = 0; j < 8; ++j) {
            int s = t + j * 128;
            int k = s >> 4, c4 = (s & 15) * 4;
            *(float4 *)&Ws[k][c4] =
                *(const float4 *)(g_Wc + (kt * 64 + k) * 64 + c4);
        }
        __syncthreads();

#pragma unroll 8
        for (int k = 0; k < 64; ++k) {
            float4 xa = *(const float4 *)&XsT[k][r0];
            float4 xb = *(const float4 *)&XsT[k][r0 + 4];
            ulonglong2 wA = *(const ulonglong2 *)&Ws[k][c0];
            ulonglong2 wB = *(const ulonglong2 *)&Ws[k][c0 + 4];
            float xs[8] = {xa.x, xa.y, xa.z, xa.w, xb.x, xb.y, xb.z, xb.w};
#pragma unroll
            for (int r = 0; r < 8; ++r) {
                unsigned long long xd = bcast2(xs[r]);
                fma2(acc[r][0], xd, wA.x);
                fma2(acc[r][1], xd, wA.y);
                fma2(acc[r][2], xd, wB.x);
                fma2(acc[r][3], xd, wB.y);
            }
        }
        __syncthreads();
    }

    ulonglong2 bA = *(const ulonglong2 *)(bias1 + c0);
    ulonglong2 bB = *(const ulonglong2 *)(bias1 + c0 + 4);
#pragma unroll
    for (int r = 0; r < 8; ++r) {
        int grow = rowbase + r0 + r;
        if (grow < n) {
            float sc = rsqrtf(fmaxf((float)g_dego[grow], 1.f));
            unsigned long long sd = bcast2(sc);
            add2(acc[r][0], bA.x); add2(acc[r][1], bA.y);
            add2(acc[r][2], bB.x); add2(acc[r][3], bB.y);
            mul2(acc[r][0], sd); mul2(acc[r][1], sd);
            mul2(acc[r][2], sd); mul2(acc[r][3], sd);
            float *p = g_hs + grow * 64 + c0;
            *(ulonglong2 *)p       = make_ulonglong2(acc[r][0], acc[r][1]);
            *(ulonglong2 *)(p + 4) = make_ulonglong2(acc[r][2], acc[r][3]);
        }
    }
}

// ---------------------------------------------------------------------------
// Layer-2 aggregation: agg2[d] = rsqrt(deg_in) * sum over dst-row of hs[src]
// ---------------------------------------------------------------------------
__global__ void row_agg2_kernel(int n) {
    int idx = blockIdx.x * blockDim.x + threadIdx.x;
    int d = idx >> 3;
    if (d >= n) return;
    int lane = idx & 7;
    int lo = g_rowptr[d * 8], hi = g_rowptr[d * 8 + 8];
    float4 a0 = make_float4(0.f, 0.f, 0.f, 0.f);
    float4 a1 = make_float4(0.f, 0.f, 0.f, 0.f);
    int i = lo;
    for (; i + 1 < hi; i += 2) {
        int s0 = g_csr_src[i], s1 = g_csr_src[i + 1];
        const float4 *p0 = (const float4 *)(g_hs + s0 * 64 + lane * 8);
        const float4 *p1 = (const float4 *)(g_hs + s1 * 64 + lane * 8);
        float4 u0 = p0[0], u1 = p0[1], v0 = p1[0], v1 = p1[1];
        a0.x += u0.x + v0.x; a0.y += u0.y + v0.y;
        a0.z += u0.z + v0.z; a0.w += u0.w + v0.w;
        a1.x += u1.x + v1.x; a1.y += u1.y + v1.y;
        a1.z += u1.z + v1.z; a1.w += u1.w + v1.w;
    }
    if (i < hi) {
        int s = g_csr_src[i];
        const float4 *p = (const float4 *)(g_hs + s * 64 + lane * 8);
        float4 u0 = p[0], u1 = p[1];
        a0.x += u0.x; a0.y += u0.y; a0.z += u0.z; a0.w += u0.w;
        a1.x += u1.x; a1.y += u1.y; a1.z += u1.z; a1.w += u1.w;
    }
    float sc = rsqrtf(fmaxf((float)(hi - lo), 1.f));
    a0.x *= sc; a0.y *= sc; a0.z *= sc; a0.w *= sc;
    a1.x *= sc; a1.y *= sc; a1.z *= sc; a1.w *= sc;
    float4 *q = (float4 *)(g_agg2 + d * 64 + lane * 8);
    q[0] = a0; q[1] = a1;
}

// ---------------------------------------------------------------------------
// GEMM 2: out[N,64] = agg2 @ W2 + bias2  (agg2 pre-scaled)
// ---------------------------------------------------------------------------
__global__ __launch_bounds__(128) void gemm2_kernel(const float *__restrict__ W2,
                                                    const float *__restrict__ bias2,
                                                    float *__restrict__ out,
                                                    int n) {
    __shared__ __align__(16) float XsT[64][128];
    __shared__ __align__(16) float Ws[64][64];
    int t = threadIdx.x;
    int rowbase = blockIdx.x * 128;

    {
        int row = rowbase + t;
        const float4 *xp = (const float4 *)(g_agg2 + (long long)row * 64);
#pragma unroll
        for (int cg = 0; cg < 16; ++cg) {
            float4 v = (row < n) ? xp[cg] : make_float4(0.f, 0.f, 0.f, 0.f);
            XsT[cg * 4 + 0][t] = v.x;
            XsT[cg * 4 + 1][t] = v.y;
            XsT[cg * 4 + 2][t] = v.z;
            XsT[cg * 4 + 3][t] = v.w;
        }
    }
#pragma unroll
    for (int j = 0; j < 8; ++j) {
        int s = t + j * 128;
        int k = s >> 4, c4 = (s & 15) * 4;
        *(float4 *)&Ws[k][c4] = *(const float4 *)(W2 + k * 64 + c4);
    }
    __syncthreads();

    int tc = t & 7, tr = t >> 3;
    int c0 = tc * 8, r0 = tr * 8;

    unsigned long long acc[8][4];
#pragma unroll
    for (int r = 0; r < 8; ++r)
#pragma unroll
        for (int j = 0; j < 4; ++j) acc[r][j] = 0ULL;

#pragma unroll 8
    for (int k = 0; k < 64; ++k) {
        float4 xa = *(const float4 *)&XsT[k][r0];
        float4 xb = *(const float4 *)&XsT[k][r0 + 4];
        ulonglong2 wA = *(const ulonglong2 *)&Ws[k][c0];
        ulonglong2 wB = *(const ulonglong2 *)&Ws[k][c0 + 4];
        float xs[8] = {xa.x, xa.y, xa.z, xa.w, xb.x, xb.y, xb.z, xb.w};
#pragma unroll
        for (int r = 0; r < 8; ++r) {
            unsigned long long xd = bcast2(xs[r]);
            fma2(acc[r][0], xd, wA.x);
            fma2(acc[r][1], xd, wA.y);
            fma2(acc[r][2], xd, wB.x);
            fma2(acc[r][3], xd, wB.y);
        }
    }

    ulonglong2 bA = *(const ulonglong2 *)(bias2 + c0);
    ulonglong2 bB = *(const ulonglong2 *)(bias2 + c0 + 4);
#pragma unroll
    for (int r = 0; r < 8; ++r) {
        add2(acc[r][0], bA.x); add2(acc[r][1], bA.y);
        add2(acc[r][2], bB.x); add2(acc[r][3], bB.y);
        int grow = rowbase + r0 + r;
        if (grow < n) {
            float *p = out + grow * 64 + c0;
            *(ulonglong2 *)p       = make_ulonglong2(acc[r][0], acc[r][1]);
            *(ulonglong2 *)(p + 4) = make_ulonglong2(acc[r][2], acc[r][3]);
        }
    }
}

// ---------------------------------------------------------------------------
// Launcher.  Inputs (metadata order):
//  0 node_features [N,64] f32 | 1 edge_index [2,E] i32 | 2 edge_norm (UNUSED)
//  3 edge_type [E] i32 | 4 basis [30,64,64] | 5 comp [8,30]
//  6 loop_weight [64,64] | 7 bias1 [64] | 8 weight2 [64,64] | 9 bias2 [64]
// ---------------------------------------------------------------------------
extern "C" void kernel_launch(void *const *d_in, const int *in_sizes, int n_in,
                              void *d_out, int out_size) {
    const float *x     = (const float *)d_in[0];
    const int *ei      = (const int *)d_in[1];
    const int *et      = (const int *)d_in[3];
    const float *basis = (const float *)d_in[4];
    const float *comp  = (const float *)d_in[5];
    const float *loopw = (const float *)d_in[6];
    const float *bias1 = (const float *)d_in[7];
    const float *w2    = (const float *)d_in[8];
    const float *bias2 = (const float *)d_in[9];
    float *out = (float *)d_out;

    int n = in_sizes[0] / 64;
    int E = in_sizes[2];
    int rb = (n + 127) / 128;

    zero_kernel<<<(NSEG + 255) / 256, 256>>>();
    build_w_kernel<<<(576 * 64 + 255) / 256, 256>>>(basis, comp, loopw);
    hist_kernel<<<(E + 255) / 256, 256>>>(ei, et, E);

    scan_block_kernel<<<NBLK, SCAN_BLK>>>();
    scan_top_kernel<<<1, 512>>>();
    scan_add_kernel<<<NBLK, SCAN_BLK>>>(E);
    fill_kernel<<<(E + 255) / 256, 256>>>(ei, et, E);

    seg_agg_kernel<<<(NSEG * 8 + 255) / 256, 256>>>(x);
    gemmA_kernel<<<rb, 128>>>(x, bias1, n);

    row_agg2_kernel<<<(n * 8 + 255) / 256, 256>>>(n);
    gemm2_kernel<<<rb, 128>>>(w2, bias2, out, n);
}